// round 1
// baseline (speedup 1.0000x reference)
#include <cuda_runtime.h>
#include <cstdint>

// ---- Problem constants -----------------------------------------------------
#define BB 16
#define NN 8192
#define NIN 4096
#define DD 8
#define BN (BB * NN)          // 131072
#define KTOT (NN + NIN)       // 12288 virtual rows (W_int then W_ext)

// alpha = exp(-1e-3/0.02), rho_a = exp(-1e-3/0.2)
#define ALPHA_F 0.9512294245007140f
#define ONE_MINUS_ALPHA_F (1.0f - 0.9512294245007140f)
#define RHO_A_F 0.9950124791926823f
#define BETA_F 1.8f
#define TH0_F 1.0f

// ---- Device scratch (static, allowed) -------------------------------------
__device__ int g_list[BB][KTOT];   // active virtual-row list per batch
__device__ int g_cnt[BB];

// ---- Kernel 1: deterministic per-batch active-row list (warp ballot) ------
__global__ void build_lists(const float* __restrict__ Xd,
                            const float* __restrict__ Xext) {
    int b = blockIdx.x;         // one block (one warp) per batch
    int lane = threadIdx.x;     // 0..31
    int* list = g_list[b];
    int base = 0;

    // Internal rows: Xd[-1] == slot 7, layout [D,B,N]
    const float* xrow = Xd + ((size_t)(7 * BB + b)) * NN;
    for (int k0 = 0; k0 < NN; k0 += 32) {
        float v = xrow[k0 + lane];
        unsigned m = __ballot_sync(0xffffffffu, v > 0.5f);
        if (v > 0.5f) {
            int pos = base + __popc(m & ((1u << lane) - 1u));
            list[pos] = k0 + lane;
        }
        base += __popc(m);
    }
    // External rows
    const float* erow = Xext + (size_t)b * NIN;
    for (int k0 = 0; k0 < NIN; k0 += 32) {
        float v = erow[k0 + lane];
        unsigned m = __ballot_sync(0xffffffffu, v > 0.5f);
        if (v > 0.5f) {
            int pos = base + __popc(m & ((1u << lane) - 1u));
            list[pos] = NN + k0 + lane;
        }
        base += __popc(m);
    }
    if (lane == 0) g_cnt[b] = base;
}

// ---- Kernel 2: elementwise spike gen + adaptation + delay-buffer shift ----
// out layout: X [0,BN) | V_new [BN,2BN) | a_new [2BN,3BN) | Xd_new [3BN,11BN)
__global__ void prep_elem(const float* __restrict__ V,
                          const float* __restrict__ a,
                          const float* __restrict__ Xd,
                          float* __restrict__ out) {
    int i = blockIdx.x * blockDim.x + threadIdx.x;
    if (i < BN) {
        float av = a[i];
        float x = (V[i] >= TH0_F + BETA_F * av) ? 1.0f : 0.0f;
        out[i] = x;                           // X
        out[2 * BN + i] = RHO_A_F * av + x;   // a_new
        out[3 * BN + i] = x;                  // Xd_new slot 0
    }
    if (i < 7 * BN) {
        out[3 * BN + BN + i] = Xd[i];         // Xd_new slots 1..7 = old 0..6
    }
}

// ---- Kernel 3: sparse row-sum "GEMM" + fused membrane epilogue ------------
// grid: (N/512 col-tiles, B). 128 threads, float4 per thread = 512 cols/CTA.
__global__ __launch_bounds__(128)
void spmm_kernel(const float* __restrict__ V,
                 const float* __restrict__ a,
                 const float* __restrict__ Wint,
                 const float* __restrict__ Wext,
                 float* __restrict__ out) {
    int b = blockIdx.y;
    int j = blockIdx.x * 512 + threadIdx.x * 4;

    int cnt = g_cnt[b];
    const int* list = g_list[b];

    float4 acc = make_float4(0.f, 0.f, 0.f, 0.f);

    int i = 0;
    // Unroll by 4: 4 independent float4 loads in flight (MLP)
    for (; i + 4 <= cnt; i += 4) {
        int k0 = list[i + 0];
        int k1 = list[i + 1];
        int k2 = list[i + 2];
        int k3 = list[i + 3];
        const float* r0 = (k0 < NN) ? (Wint + (size_t)k0 * NN)
                                    : (Wext + (size_t)(k0 - NN) * NN);
        const float* r1 = (k1 < NN) ? (Wint + (size_t)k1 * NN)
                                    : (Wext + (size_t)(k1 - NN) * NN);
        const float* r2 = (k2 < NN) ? (Wint + (size_t)k2 * NN)
                                    : (Wext + (size_t)(k2 - NN) * NN);
        const float* r3 = (k3 < NN) ? (Wint + (size_t)k3 * NN)
                                    : (Wext + (size_t)(k3 - NN) * NN);
        float4 w0 = *(const float4*)(r0 + j);
        float4 w1 = *(const float4*)(r1 + j);
        float4 w2 = *(const float4*)(r2 + j);
        float4 w3 = *(const float4*)(r3 + j);
        acc.x += w0.x; acc.y += w0.y; acc.z += w0.z; acc.w += w0.w;
        acc.x += w1.x; acc.y += w1.y; acc.z += w1.z; acc.w += w1.w;
        acc.x += w2.x; acc.y += w2.y; acc.z += w2.z; acc.w += w2.w;
        acc.x += w3.x; acc.y += w3.y; acc.z += w3.z; acc.w += w3.w;
    }
    for (; i < cnt; i++) {
        int k = list[i];
        const float* r = (k < NN) ? (Wint + (size_t)k * NN)
                                  : (Wext + (size_t)(k - NN) * NN);
        float4 w = *(const float4*)(r + j);
        acc.x += w.x; acc.y += w.y; acc.z += w.z; acc.w += w.w;
    }

    // Fused membrane epilogue: V_new = ALPHA*V*(1-X) + (1-ALPHA)*current
    size_t idx = (size_t)b * NN + j;
    float4 Vv = *(const float4*)(V + idx);
    float4 av = *(const float4*)(a + idx);
    float4 vn;
    {
        float x = (Vv.x >= TH0_F + BETA_F * av.x) ? 1.0f : 0.0f;
        vn.x = ALPHA_F * Vv.x * (1.0f - x) + ONE_MINUS_ALPHA_F * acc.x;
        x = (Vv.y >= TH0_F + BETA_F * av.y) ? 1.0f : 0.0f;
        vn.y = ALPHA_F * Vv.y * (1.0f - x) + ONE_MINUS_ALPHA_F * acc.y;
        x = (Vv.z >= TH0_F + BETA_F * av.z) ? 1.0f : 0.0f;
        vn.z = ALPHA_F * Vv.z * (1.0f - x) + ONE_MINUS_ALPHA_F * acc.z;
        x = (Vv.w >= TH0_F + BETA_F * av.w) ? 1.0f : 0.0f;
        vn.w = ALPHA_F * Vv.w * (1.0f - x) + ONE_MINUS_ALPHA_F * acc.w;
    }
    *(float4*)(out + BN + idx) = vn;   // V_new region
}

// ---- Launch ----------------------------------------------------------------
extern "C" void kernel_launch(void* const* d_in, const int* in_sizes, int n_in,
                              void* d_out, int out_size) {
    const float* V    = (const float*)d_in[0];   // [B,N]
    const float* a    = (const float*)d_in[1];   // [B,N]
    const float* Xd   = (const float*)d_in[2];   // [D,B,N]
    const float* Xext = (const float*)d_in[3];   // [B,N_IN]
    const float* Wint = (const float*)d_in[4];   // [N,N]
    const float* Wext = (const float*)d_in[5];   // [N_IN,N]
    float* out = (float*)d_out;

    build_lists<<<BB, 32>>>(Xd, Xext);

    int total = 7 * BN;  // covers both the BN elementwise part and the copy
    prep_elem<<<(total + 255) / 256, 256>>>(V, a, Xd, out);

    dim3 grid(NN / 512, BB);
    spmm_kernel<<<grid, 128>>>(V, a, Wint, Wext, out);
}

// round 3
// speedup vs baseline: 2.7229x; 2.7229x over previous
#include <cuda_runtime.h>
#include <cstdint>

// ---- Problem constants -----------------------------------------------------
#define BB 16
#define NN 8192
#define NIN 4096
#define DD 8
#define BN (BB * NN)          // 131072
#define KTOT (NN + NIN)       // 12288 virtual rows (W_int then W_ext)
#define NSPLIT 4
#define SEG_MAX ((KTOT + NSPLIT - 1) / NSPLIT)   // 3072

#define ALPHA_F 0.9512294245007140f
#define ONE_MINUS_ALPHA_F (1.0f - 0.9512294245007140f)
#define RHO_A_F 0.9950124791926823f
#define BETA_F 1.8f
#define TH0_F 1.0f

// ---- Device scratch (static globals, allowed) ------------------------------
__device__ int   g_list[BB][KTOT];
__device__ int   g_cnt[BB];
__device__ float g_partial[NSPLIT * BB * NN];    // 2 MB split-K partials

// ---- Kernel 1: parallel per-batch active-row list --------------------------
// 1 block per batch, 512 threads (16 warps). Each warp owns 768 virtual rows
// (24 ballot groups). All 24 loads issued upfront (MLP=24), then a 2-phase
// block scan. Deterministic ordering (row-index order).
__global__ __launch_bounds__(512)
void build_lists(const float* __restrict__ Xd,
                 const float* __restrict__ Xext) {
    int b = blockIdx.x;
    int tid = threadIdx.x;
    int w = tid >> 5;
    int lane = tid & 31;

    __shared__ int s_woff[16];
    __shared__ int s_total;

    const int base_k = w * (KTOT / 16);   // 768 per warp; 32-aligned groups

    float v[24];
#pragma unroll
    for (int u = 0; u < 24; u++) {
        int k = base_k + u * 32 + lane;
        // each 32-group is entirely internal or entirely external (8192%32==0)
        if (k < NN)
            v[u] = Xd[((size_t)(7 * BB + b)) * NN + k];
        else
            v[u] = Xext[(size_t)b * NIN + (k - NN)];
    }

    unsigned m[24];
    int cnt = 0;
#pragma unroll
    for (int u = 0; u < 24; u++) {
        m[u] = __ballot_sync(0xffffffffu, v[u] > 0.5f);
        cnt += __popc(m[u]);
    }
    if (lane == 0) s_woff[w] = cnt;
    __syncthreads();

    if (w == 0 && lane < 16) {
        int val = s_woff[lane];
        int incl = val;
#pragma unroll
        for (int d = 1; d < 16; d <<= 1) {
            int o = __shfl_up_sync(0xffffu, incl, d, 16);
            if (lane >= d) incl += o;
        }
        s_woff[lane] = incl - val;          // exclusive
        if (lane == 15) s_total = incl;
    }
    __syncthreads();

    int pos = s_woff[w];
    int* list = g_list[b];
    unsigned lt = (1u << lane) - 1u;
#pragma unroll
    for (int u = 0; u < 24; u++) {
        if (v[u] > 0.5f)
            list[pos + __popc(m[u] & lt)] = base_k + u * 32 + lane;
        pos += __popc(m[u]);
    }
    if (tid == 0) g_cnt[b] = s_total;
}

// ---- Kernel 2: elementwise spike gen + adaptation + delay-buffer shift ----
// out layout: X [0,BN) | V_new [BN,2BN) | a_new [2BN,3BN) | Xd_new [3BN,11BN)
__global__ void prep_elem(const float* __restrict__ V,
                          const float* __restrict__ a,
                          const float* __restrict__ Xd,
                          float* __restrict__ out) {
    int i = blockIdx.x * blockDim.x + threadIdx.x;
    if (i < BN) {
        float av = a[i];
        float x = (V[i] >= TH0_F + BETA_F * av) ? 1.0f : 0.0f;
        out[i] = x;                           // X
        out[2 * BN + i] = RHO_A_F * av + x;   // a_new
        out[3 * BN + i] = x;                  // Xd_new slot 0
    }
    if (i < 7 * BN) {
        out[4 * BN + i] = Xd[i];              // Xd_new slots 1..7 = old 0..6
    }
}

// ---- Kernel 3: split-K sparse row-sum --------------------------------------
// grid (N/512 col-tiles, B, NSPLIT); 128 threads, float4/thread = 512 cols.
// List segment staged in smem; unroll 8 for MLP.
__global__ __launch_bounds__(128)
void spmm_kernel(const float* __restrict__ Wint,
                 const float* __restrict__ Wext) {
    int b = blockIdx.y;
    int z = blockIdx.z;
    int j = blockIdx.x * 512 + threadIdx.x * 4;

    __shared__ int s_list[SEG_MAX];

    int cnt = g_cnt[b];
    int seg = (cnt + NSPLIT - 1) / NSPLIT;
    int start = z * seg;
    int end = start + seg;
    if (end > cnt) end = cnt;
    int len = end - start;
    if (len < 0) len = 0;

    const int* list = g_list[b] + start;
    for (int i = threadIdx.x; i < len; i += 128) s_list[i] = list[i];
    __syncthreads();

    float4 acc = make_float4(0.f, 0.f, 0.f, 0.f);

    int i = 0;
    for (; i + 8 <= len; i += 8) {
        const float* r[8];
#pragma unroll
        for (int u = 0; u < 8; u++) {
            int k = s_list[i + u];
            r[u] = (k < NN) ? (Wint + ((size_t)k << 13))
                            : (Wext + ((size_t)(k - NN) << 13));
        }
        float4 wv[8];
#pragma unroll
        for (int u = 0; u < 8; u++) wv[u] = *(const float4*)(r[u] + j);
#pragma unroll
        for (int u = 0; u < 8; u++) {
            acc.x += wv[u].x; acc.y += wv[u].y;
            acc.z += wv[u].z; acc.w += wv[u].w;
        }
    }
    for (; i < len; i++) {
        int k = s_list[i];
        const float* r = (k < NN) ? (Wint + ((size_t)k << 13))
                                  : (Wext + ((size_t)(k - NN) << 13));
        float4 wv = *(const float4*)(r + j);
        acc.x += wv.x; acc.y += wv.y; acc.z += wv.z; acc.w += wv.w;
    }

    *(float4*)(g_partial + ((size_t)z * BB + b) * NN + j) = acc;
}

// ---- Kernel 4: split-K reduce + fused membrane epilogue --------------------
__global__ __launch_bounds__(256)
void reduce_kernel(const float* __restrict__ V,
                   const float* __restrict__ a,
                   float* __restrict__ out) {
    int t = blockIdx.x * blockDim.x + threadIdx.x;   // one float4 per thread
    size_t idx = (size_t)t * 4;
    if (idx >= BN) return;

    float4 s0 = *(const float4*)(g_partial + 0 * (size_t)BN + idx);
    float4 s1 = *(const float4*)(g_partial + 1 * (size_t)BN + idx);
    float4 s2 = *(const float4*)(g_partial + 2 * (size_t)BN + idx);
    float4 s3 = *(const float4*)(g_partial + 3 * (size_t)BN + idx);
    float4 cur;
    cur.x = (s0.x + s1.x) + (s2.x + s3.x);
    cur.y = (s0.y + s1.y) + (s2.y + s3.y);
    cur.z = (s0.z + s1.z) + (s2.z + s3.z);
    cur.w = (s0.w + s1.w) + (s2.w + s3.w);

    float4 Vv = *(const float4*)(V + idx);
    float4 av = *(const float4*)(a + idx);
    float4 vn;
    float x;
    x = (Vv.x >= TH0_F + BETA_F * av.x) ? 1.0f : 0.0f;
    vn.x = ALPHA_F * Vv.x * (1.0f - x) + ONE_MINUS_ALPHA_F * cur.x;
    x = (Vv.y >= TH0_F + BETA_F * av.y) ? 1.0f : 0.0f;
    vn.y = ALPHA_F * Vv.y * (1.0f - x) + ONE_MINUS_ALPHA_F * cur.y;
    x = (Vv.z >= TH0_F + BETA_F * av.z) ? 1.0f : 0.0f;
    vn.z = ALPHA_F * Vv.z * (1.0f - x) + ONE_MINUS_ALPHA_F * cur.z;
    x = (Vv.w >= TH0_F + BETA_F * av.w) ? 1.0f : 0.0f;
    vn.w = ALPHA_F * Vv.w * (1.0f - x) + ONE_MINUS_ALPHA_F * cur.w;

    *(float4*)(out + BN + idx) = vn;   // V_new region
}

// ---- Launch ----------------------------------------------------------------
extern "C" void kernel_launch(void* const* d_in, const int* in_sizes, int n_in,
                              void* d_out, int out_size) {
    const float* V    = (const float*)d_in[0];
    const float* a    = (const float*)d_in[1];
    const float* Xd   = (const float*)d_in[2];
    const float* Xext = (const float*)d_in[3];
    const float* Wint = (const float*)d_in[4];
    const float* Wext = (const float*)d_in[5];
    float* out = (float*)d_out;

    build_lists<<<BB, 512>>>(Xd, Xext);

    int total = 7 * BN;
    prep_elem<<<(total + 255) / 256, 256>>>(V, a, Xd, out);

    dim3 grid(NN / 512, BB, NSPLIT);
    spmm_kernel<<<grid, 128>>>(Wint, Wext);

    reduce_kernel<<<(BN / 4 + 255) / 256, 256>>>(V, a, out);
}